// round 1
// baseline (speedup 1.0000x reference)
#include <cuda_runtime.h>
#include <math_constants.h>

// Problem constants
#define BB   4
#define NN   4096
#define CIN  64
#define COUT 128
#define KP   15
#define KNNK 16
#define KDIM (KP * CIN)   // 960

// ---------------- device scratch (no cudaMalloc allowed) ----------------
__device__ float4 g_coordsT[BB * NN];                 // 256 KB  (x,y,z,pad) point-major
__device__ float  g_featT[BB * NN * CIN];             // 4 MB    features point-major
__device__ int    g_nbr[BB * NN * KNNK];              // 1 MB    knn indices
__device__ float  g_agg[(size_t)BB * NN * KDIM];      // 63 MB   aggregated features

// ---------------- stage 0a: coords (B,3,N) -> float4 AoS ----------------
__global__ void prep_coords_kernel(const float* __restrict__ coords) {
    int i = blockIdx.x * blockDim.x + threadIdx.x;   // 0..16383
    int b = i >> 12;
    int n = i & (NN - 1);
    const float* cb = coords + (size_t)b * 3 * NN;
    g_coordsT[i] = make_float4(cb[n], cb[NN + n], cb[2 * NN + n], 0.0f);
}

// ---------------- stage 0b: features (B,C,N) -> (B,N,C) tiled transpose ----------------
__global__ void prep_feat_kernel(const float* __restrict__ feats) {
    __shared__ float tile[32][33];
    int b  = blockIdx.z;
    int n0 = blockIdx.x * 32;
    int c0 = blockIdx.y * 32;
    int tx = threadIdx.x;       // 0..31
    int ty = threadIdx.y;       // 0..7
    const float* fb = feats + (size_t)b * CIN * NN;
    #pragma unroll
    for (int r = 0; r < 32; r += 8)
        tile[ty + r][tx] = fb[(size_t)(c0 + ty + r) * NN + n0 + tx];
    __syncthreads();
    float* ob = g_featT + (size_t)b * NN * CIN;
    #pragma unroll
    for (int r = 0; r < 32; r += 8)
        ob[(size_t)(n0 + ty + r) * CIN + c0 + tx] = tile[tx][ty + r];
}

// ---------------- stage 1: brute-force KNN (1 thread per query) ----------------
__global__ void knn_kernel() {
    __shared__ float4 s[128];
    int i = blockIdx.x * 128 + threadIdx.x;   // flat query id; blocks never straddle batches
    int b = i >> 12;
    int n = i & (NN - 1);
    float4 q = g_coordsT[i];

    float bd[KNNK];
    int   bi[KNNK];
    #pragma unroll
    for (int t = 0; t < KNNK; t++) { bd[t] = CUDART_INF_F; bi[t] = -1; }
    float worst = CUDART_INF_F;
    int   ws = 0;

    const float4* base = g_coordsT + (b << 12);
    for (int t0 = 0; t0 < NN; t0 += 128) {
        __syncthreads();
        s[threadIdx.x] = base[t0 + threadIdx.x];
        __syncthreads();
        #pragma unroll 4
        for (int j = 0; j < 128; j++) {
            float4 c = s[j];
            float dx = q.x - c.x, dy = q.y - c.y, dz = q.z - c.z;
            float d2 = dx * dx + dy * dy + dz * dz;
            int   m  = t0 + j;
            if (d2 < worst && m != n) {
                // predicated static-index replace (keeps arrays in registers)
                #pragma unroll
                for (int t = 0; t < KNNK; t++)
                    if (t == ws) { bd[t] = d2; bi[t] = m; }
                // rescan for new worst
                worst = bd[0]; ws = 0;
                #pragma unroll
                for (int t = 1; t < KNNK; t++)
                    if (bd[t] > worst) { worst = bd[t]; ws = t; }
            }
        }
    }
    #pragma unroll
    for (int t = 0; t < KNNK; t++)
        g_nbr[(size_t)i * KNNK + t] = bi[t];
}

// ---------------- stage 2: influence + aggregation ----------------
// One block (64 threads) per point. Thread tid handles channel c=tid.
// agg[p][c] = sum_k infl[k][p] * feat[nbr_k][c], written as K index p*64+c
// which matches kernel_weights (15,64,128) flattened row-major.
__global__ void agg_kernel(const float* __restrict__ kpts) {
    __shared__ int   nbr[KNNK];
    __shared__ float diffs[KNNK][3];
    __shared__ float kps[KP * 3];
    __shared__ float infl[KNNK][KP];

    int m   = blockIdx.x;          // flat point id (b*4096+n)
    int b   = m >> 12;
    int tid = threadIdx.x;

    if (tid < KP * 3) kps[tid] = kpts[tid];
    if (tid < KNNK)   nbr[tid] = g_nbr[(size_t)m * KNNK + tid];
    __syncthreads();
    if (tid < KNNK) {
        float4 q = g_coordsT[m];
        float4 c = g_coordsT[(b << 12) + nbr[tid]];
        diffs[tid][0] = c.x - q.x;
        diffs[tid][1] = c.y - q.y;
        diffs[tid][2] = c.z - q.z;
    }
    __syncthreads();
    for (int t = tid; t < KNNK * KP; t += 64) {
        int kk = t / KP, p = t % KP;
        float dx = diffs[kk][0] - kps[p * 3 + 0];
        float dy = diffs[kk][1] - kps[p * 3 + 1];
        float dz = diffs[kk][2] - kps[p * 3 + 2];
        float sq = dx * dx + dy * dy + dz * dz;
        infl[kk][p] = expf(-sq * 100.0f);   // 1/SIGMA^2 = 100
    }
    __syncthreads();

    float a[KP];
    #pragma unroll
    for (int p = 0; p < KP; p++) a[p] = 0.0f;

    for (int kk = 0; kk < KNNK; kk++) {
        float f = g_featT[((size_t)(b << 12) + nbr[kk]) * CIN + tid];
        #pragma unroll
        for (int p = 0; p < KP; p++)
            a[p] += infl[kk][p] * f;
    }
    float* outp = g_agg + (size_t)m * KDIM;
    #pragma unroll
    for (int p = 0; p < KP; p++)
        outp[p * CIN + tid] = a[p];   // coalesced per p
}

// ---------------- stage 3: SGEMM  out(16384x128) = Agg(16384x960) @ W(960x128) ----------------
// 128x128 block tile, BK=16, 256 threads, 8x8 microtile per thread.
__global__ __launch_bounds__(256) void gemm_kernel(const float* __restrict__ W,
                                                   const float* __restrict__ bias,
                                                   float* __restrict__ out) {
    __shared__ float As[16][128];   // As[k][m]
    __shared__ float Bs[16][128];   // Bs[k][n]

    int m0  = blockIdx.x * 128;
    int tid = threadIdx.x;
    int tx  = tid & 15;             // col group
    int ty  = tid >> 4;             // row group

    float acc[8][8];
    #pragma unroll
    for (int i = 0; i < 8; i++)
        #pragma unroll
        for (int j = 0; j < 8; j++) acc[i][j] = 0.0f;

    const float* Ab = g_agg + (size_t)m0 * KDIM;
    int arow  = tid >> 2;           // 0..63
    int acol4 = (tid & 3) * 4;      // 0,4,8,12

    for (int k0 = 0; k0 < KDIM; k0 += 16) {
        // load A tile (transposed into smem)
        #pragma unroll
        for (int r = 0; r < 2; r++) {
            int row = arow + r * 64;
            float4 v = *(const float4*)(Ab + (size_t)row * KDIM + k0 + acol4);
            As[acol4 + 0][row] = v.x;
            As[acol4 + 1][row] = v.y;
            As[acol4 + 2][row] = v.z;
            As[acol4 + 3][row] = v.w;
        }
        // load B tile
        #pragma unroll
        for (int r = 0; r < 2; r++) {
            int lin = tid + r * 256;             // float4 units
            int k   = lin >> 5;
            int n4  = (lin & 31) * 4;
            *(float4*)&Bs[k][n4] = *(const float4*)(W + (size_t)(k0 + k) * COUT + n4);
        }
        __syncthreads();

        #pragma unroll
        for (int k = 0; k < 16; k++) {
            float a[8], bf[8];
            #pragma unroll
            for (int i = 0; i < 8; i++) a[i] = As[k][ty * 8 + i];
            #pragma unroll
            for (int j = 0; j < 8; j++) bf[j] = Bs[k][tx * 8 + j];
            #pragma unroll
            for (int i = 0; i < 8; i++)
                #pragma unroll
                for (int j = 0; j < 8; j++)
                    acc[i][j] += a[i] * bf[j];
        }
        __syncthreads();
    }

    // epilogue: out is (B, C_out, N); within an M tile all rows share batch b
    int b     = m0 >> 12;
    int nbase = (m0 & (NN - 1)) + ty * 8;
    #pragma unroll
    for (int j = 0; j < 8; j++) {
        int o = tx * 8 + j;
        float bv = bias[o];
        float* op = out + ((size_t)b * COUT + o) * NN + nbase;
        float4 v0 = make_float4(acc[0][j] + bv, acc[1][j] + bv, acc[2][j] + bv, acc[3][j] + bv);
        float4 v1 = make_float4(acc[4][j] + bv, acc[5][j] + bv, acc[6][j] + bv, acc[7][j] + bv);
        *(float4*)(op)     = v0;
        *(float4*)(op + 4) = v1;
    }
}

// ---------------- launch ----------------
extern "C" void kernel_launch(void* const* d_in, const int* in_sizes, int n_in,
                              void* d_out, int out_size) {
    const float* coords        = (const float*)d_in[0];   // (4,3,4096)
    const float* features      = (const float*)d_in[1];   // (4,64,4096)
    const float* kernel_points = (const float*)d_in[2];   // (15,3)
    const float* kernel_w      = (const float*)d_in[3];   // (15,64,128)
    const float* bias          = (const float*)d_in[4];   // (128,)
    float* out = (float*)d_out;                           // (4,128,4096)

    prep_coords_kernel<<<BB * NN / 256, 256>>>(coords);
    prep_feat_kernel<<<dim3(NN / 32, CIN / 32, BB), dim3(32, 8)>>>(features);
    knn_kernel<<<BB * NN / 128, 128>>>();
    agg_kernel<<<BB * NN, 64>>>(kernel_points);
    gemm_kernel<<<BB * NN / 128, 256>>>(kernel_w, bias, out);
}

// round 2
// speedup vs baseline: 1.0716x; 1.0716x over previous
#include <cuda_runtime.h>
#include <math_constants.h>

// Problem constants
#define BB   4
#define NN   4096
#define CIN  64
#define COUT 128
#define KP   15
#define KNNK 16
#define KDIM (KP * CIN)   // 960

// ---------------- device scratch (no cudaMalloc allowed) ----------------
__device__ float4 g_coordsT[BB * NN];                 // (x,y,z,|c|^2) point-major
__device__ float  g_featT[BB * NN * CIN];             // features point-major
__device__ int    g_nbr[BB * NN * KNNK];              // knn indices
__device__ float  g_agg[(size_t)BB * NN * KDIM];      // aggregated features (63 MB)

// f32x2 packed-fma helpers (sm_100a)
__device__ __forceinline__ unsigned long long pack2(float x) {
    unsigned long long r;
    asm("mov.b64 %0, {%1, %1};" : "=l"(r) : "f"(x));
    return r;
}
__device__ __forceinline__ void fma2(unsigned long long& d, unsigned long long a, unsigned long long b) {
    asm("fma.rn.f32x2 %0, %1, %2, %0;" : "+l"(d) : "l"(a), "l"(b));
}

// ---------------- stage 0a: coords (B,3,N) -> float4 AoS (+|c|^2) ----------------
__global__ void prep_coords_kernel(const float* __restrict__ coords) {
    int i = blockIdx.x * blockDim.x + threadIdx.x;   // 0..16383
    int b = i >> 12;
    int n = i & (NN - 1);
    const float* cb = coords + (size_t)b * 3 * NN;
    float x = cb[n], y = cb[NN + n], z = cb[2 * NN + n];
    g_coordsT[i] = make_float4(x, y, z, x * x + y * y + z * z);
}

// ---------------- stage 0b: features (B,C,N) -> (B,N,C) tiled transpose ----------------
__global__ void prep_feat_kernel(const float* __restrict__ feats) {
    __shared__ float tile[32][33];
    int b  = blockIdx.z;
    int n0 = blockIdx.x * 32;
    int c0 = blockIdx.y * 32;
    int tx = threadIdx.x;
    int ty = threadIdx.y;
    const float* fb = feats + (size_t)b * CIN * NN;
    #pragma unroll
    for (int r = 0; r < 32; r += 8)
        tile[ty + r][tx] = fb[(size_t)(c0 + ty + r) * NN + n0 + tx];
    __syncthreads();
    float* ob = g_featT + (size_t)b * NN * CIN;
    #pragma unroll
    for (int r = 0; r < 32; r += 8)
        ob[(size_t)(n0 + ty + r) * CIN + c0 + tx] = tile[tx][ty + r];
}

// ---------------- stage 1: KNN, 8 threads per query ----------------
// 256 threads = 32 queries x 8 slices. Each slice-thread scans 512 candidates
// (interleaved j = jj*8+si for coalesced/broadcast loads), keeping a register
// top-16 in the shifted metric d' = |c|^2 - 2 q.c  (ordering == true d2).
// Slices 1..7 dump their lists to smem; slice 0 merges them into its own list.
__global__ __launch_bounds__(256) void knn_kernel() {
    __shared__ float md[32][112];
    __shared__ int   mi[32][112];

    int tid = threadIdx.x;
    int qi  = tid >> 3;
    int si  = tid & 7;
    int q   = blockIdx.x * 32 + qi;     // 128 blocks per batch -> never straddles
    int b   = q >> 12;
    int n   = q & (NN - 1);

    const float4* base = g_coordsT + (b << 12);
    float4 qc = __ldg(&base[n]);
    float qx2 = -2.0f * qc.x, qy2 = -2.0f * qc.y, qz2 = -2.0f * qc.z;

    float bd[KNNK];
    int   bi[KNNK];
    #pragma unroll
    for (int t = 0; t < KNNK; t++) { bd[t] = CUDART_INF_F; bi[t] = -1; }
    float worst = CUDART_INF_F;
    int   ws = 0;

    #pragma unroll 4
    for (int jj = 0; jj < 512; jj++) {
        int j = (jj << 3) | si;
        float4 c = __ldg(&base[j]);
        float d = fmaf(c.x, qx2, fmaf(c.y, qy2, fmaf(c.z, qz2, c.w)));
        if (d < worst && j != n) {
            #pragma unroll
            for (int t = 0; t < KNNK; t++)
                if (t == ws) { bd[t] = d; bi[t] = j; }
            worst = bd[0]; ws = 0;
            #pragma unroll
            for (int t = 1; t < KNNK; t++)
                if (bd[t] > worst) { worst = bd[t]; ws = t; }
        }
    }

    if (si > 0) {
        #pragma unroll
        for (int t = 0; t < KNNK; t++) {
            md[qi][(si - 1) * 16 + t] = bd[t];
            mi[qi][(si - 1) * 16 + t] = bi[t];
        }
    }
    __syncthreads();

    if (si == 0) {
        for (int e = 0; e < 112; e++) {
            float d = md[qi][e];
            if (d < worst) {
                int j = mi[qi][e];
                #pragma unroll
                for (int t = 0; t < KNNK; t++)
                    if (t == ws) { bd[t] = d; bi[t] = j; }
                worst = bd[0]; ws = 0;
                #pragma unroll
                for (int t = 1; t < KNNK; t++)
                    if (bd[t] > worst) { worst = bd[t]; ws = t; }
            }
        }
        int* op = g_nbr + (size_t)q * KNNK;
        #pragma unroll
        for (int t = 0; t < KNNK; t++) op[t] = bi[t];
    }
}

// ---------------- stage 2: influence + aggregation ----------------
__global__ void agg_kernel(const float* __restrict__ kpts) {
    __shared__ int   nbr[KNNK];
    __shared__ float diffs[KNNK][3];
    __shared__ float kps[KP * 3];
    __shared__ float infl[KNNK][KP];

    int m   = blockIdx.x;
    int b   = m >> 12;
    int tid = threadIdx.x;

    if (tid < KP * 3) kps[tid] = kpts[tid];
    if (tid < KNNK)   nbr[tid] = g_nbr[(size_t)m * KNNK + tid];
    __syncthreads();
    if (tid < KNNK) {
        float4 qv = g_coordsT[m];
        float4 c  = g_coordsT[(b << 12) + nbr[tid]];
        diffs[tid][0] = c.x - qv.x;
        diffs[tid][1] = c.y - qv.y;
        diffs[tid][2] = c.z - qv.z;
    }
    __syncthreads();
    for (int t = tid; t < KNNK * KP; t += 64) {
        int kk = t / KP, p = t % KP;
        float dx = diffs[kk][0] - kps[p * 3 + 0];
        float dy = diffs[kk][1] - kps[p * 3 + 1];
        float dz = diffs[kk][2] - kps[p * 3 + 2];
        float sq = dx * dx + dy * dy + dz * dz;
        infl[kk][p] = expf(-sq * 100.0f);   // 1/SIGMA^2
    }
    __syncthreads();

    float a[KP];
    #pragma unroll
    for (int p = 0; p < KP; p++) a[p] = 0.0f;

    for (int kk = 0; kk < KNNK; kk++) {
        float f = g_featT[((size_t)(b << 12) + nbr[kk]) * CIN + tid];
        #pragma unroll
        for (int p = 0; p < KP; p++)
            a[p] += infl[kk][p] * f;
    }
    float* outp = g_agg + (size_t)m * KDIM;
    #pragma unroll
    for (int p = 0; p < KP; p++)
        outp[p * CIN + tid] = a[p];
}

// ---------------- stage 3: SGEMM via fma.rn.f32x2 ----------------
// out(16384x128) = Agg(16384x960) @ W(960x128), 128x128 tile, 256 threads,
// 8x8 microtile with accumulators packed pairwise along M. Double-buffered
// smem with register prefetch.
__global__ __launch_bounds__(256) void gemm_kernel(const float* __restrict__ W,
                                                   const float* __restrict__ bias,
                                                   float* __restrict__ out) {
    __shared__ float As[2][16][128];   // As[buf][k][m]
    __shared__ float Bs[2][16][128];   // Bs[buf][k][n]

    int m0  = blockIdx.x * 128;
    int tid = threadIdx.x;
    int tx  = tid & 15;                // n group (8 cols)
    int ty  = tid >> 4;                // m group (8 rows)

    unsigned long long acc[4][8];      // [m-pair][n]
    #pragma unroll
    for (int i = 0; i < 4; i++)
        #pragma unroll
        for (int j = 0; j < 8; j++) acc[i][j] = 0ULL;

    const float* Ab = g_agg + (size_t)m0 * KDIM;
    int arow  = tid >> 2;              // 0..63
    int acol4 = (tid & 3) * 4;         // 0,4,8,12

    float4 a_r[2], b_r[2];

    // prologue: load k-tile 0
    a_r[0] = *(const float4*)(Ab + (size_t)arow * KDIM + acol4);
    a_r[1] = *(const float4*)(Ab + (size_t)(arow + 64) * KDIM + acol4);
    {
        int l0 = tid, l1 = tid + 256;
        b_r[0] = *(const float4*)(W + (size_t)(l0 >> 5) * COUT + (l0 & 31) * 4);
        b_r[1] = *(const float4*)(W + (size_t)(l1 >> 5) * COUT + (l1 & 31) * 4);
    }
    // store to buffer 0
    {
        As[0][acol4 + 0][arow] = a_r[0].x; As[0][acol4 + 1][arow] = a_r[0].y;
        As[0][acol4 + 2][arow] = a_r[0].z; As[0][acol4 + 3][arow] = a_r[0].w;
        As[0][acol4 + 0][arow + 64] = a_r[1].x; As[0][acol4 + 1][arow + 64] = a_r[1].y;
        As[0][acol4 + 2][arow + 64] = a_r[1].z; As[0][acol4 + 3][arow + 64] = a_r[1].w;
        int l0 = tid, l1 = tid + 256;
        *(float4*)&Bs[0][l0 >> 5][(l0 & 31) * 4] = b_r[0];
        *(float4*)&Bs[0][l1 >> 5][(l1 & 31) * 4] = b_r[1];
    }
    __syncthreads();

    int buf = 0;
    const int NIT = KDIM / 16;   // 60
    for (int it = 0; it < NIT; it++) {
        if (it < NIT - 1) {
            int k0 = (it + 1) * 16;
            a_r[0] = *(const float4*)(Ab + (size_t)arow * KDIM + k0 + acol4);
            a_r[1] = *(const float4*)(Ab + (size_t)(arow + 64) * KDIM + k0 + acol4);
            int l0 = tid, l1 = tid + 256;
            b_r[0] = *(const float4*)(W + (size_t)(k0 + (l0 >> 5)) * COUT + (l0 & 31) * 4);
            b_r[1] = *(const float4*)(W + (size_t)(k0 + (l1 >> 5)) * COUT + (l1 & 31) * 4);
        }

        #pragma unroll
        for (int k = 0; k < 16; k++) {
            ulonglong2 A0 = *(const ulonglong2*)&As[buf][k][ty * 8];
            ulonglong2 A1 = *(const ulonglong2*)&As[buf][k][ty * 8 + 4];
            unsigned long long ap0 = A0.x, ap1 = A0.y, ap2 = A1.x, ap3 = A1.y;
            float4 b0 = *(const float4*)&Bs[buf][k][tx * 8];
            float4 b1 = *(const float4*)&Bs[buf][k][tx * 8 + 4];
            unsigned long long bp[8];
            bp[0] = pack2(b0.x); bp[1] = pack2(b0.y); bp[2] = pack2(b0.z); bp[3] = pack2(b0.w);
            bp[4] = pack2(b1.x); bp[5] = pack2(b1.y); bp[6] = pack2(b1.z); bp[7] = pack2(b1.w);
            #pragma unroll
            for (int j = 0; j < 8; j++) {
                fma2(acc[0][j], ap0, bp[j]);
                fma2(acc[1][j], ap1, bp[j]);
                fma2(acc[2][j], ap2, bp[j]);
                fma2(acc[3][j], ap3, bp[j]);
            }
        }

        if (it < NIT - 1) {
            buf ^= 1;
            As[buf][acol4 + 0][arow] = a_r[0].x; As[buf][acol4 + 1][arow] = a_r[0].y;
            As[buf][acol4 + 2][arow] = a_r[0].z; As[buf][acol4 + 3][arow] = a_r[0].w;
            As[buf][acol4 + 0][arow + 64] = a_r[1].x; As[buf][acol4 + 1][arow + 64] = a_r[1].y;
            As[buf][acol4 + 2][arow + 64] = a_r[1].z; As[buf][acol4 + 3][arow + 64] = a_r[1].w;
            int l0 = tid, l1 = tid + 256;
            *(float4*)&Bs[buf][l0 >> 5][(l0 & 31) * 4] = b_r[0];
            *(float4*)&Bs[buf][l1 >> 5][(l1 & 31) * 4] = b_r[1];
            __syncthreads();
        }
    }

    // epilogue: out is (B, C_out, N); m maps to n (point index)
    int b     = m0 >> 12;
    int nbase = (m0 & (NN - 1)) + ty * 8;
    #pragma unroll
    for (int j = 0; j < 8; j++) {
        int o = tx * 8 + j;
        float bv = __ldg(&bias[o]);
        float* op = out + ((size_t)b * COUT + o) * NN + nbase;
        float2 p0 = *reinterpret_cast<float2*>(&acc[0][j]);
        float2 p1 = *reinterpret_cast<float2*>(&acc[1][j]);
        float2 p2 = *reinterpret_cast<float2*>(&acc[2][j]);
        float2 p3 = *reinterpret_cast<float2*>(&acc[3][j]);
        float4 v0 = make_float4(p0.x + bv, p0.y + bv, p1.x + bv, p1.y + bv);
        float4 v1 = make_float4(p2.x + bv, p2.y + bv, p3.x + bv, p3.y + bv);
        *(float4*)(op)     = v0;
        *(float4*)(op + 4) = v1;
    }
}

// ---------------- launch ----------------
extern "C" void kernel_launch(void* const* d_in, const int* in_sizes, int n_in,
                              void* d_out, int out_size) {
    const float* coords        = (const float*)d_in[0];   // (4,3,4096)
    const float* features      = (const float*)d_in[1];   // (4,64,4096)
    const float* kernel_points = (const float*)d_in[2];   // (15,3)
    const float* kernel_w      = (const float*)d_in[3];   // (15,64,128)
    const float* bias          = (const float*)d_in[4];   // (128,)
    float* out = (float*)d_out;                           // (4,128,4096)

    prep_coords_kernel<<<BB * NN / 256, 256>>>(coords);
    prep_feat_kernel<<<dim3(NN / 32, CIN / 32, BB), dim3(32, 8)>>>(features);
    knn_kernel<<<BB * NN / 32, 256>>>();
    agg_kernel<<<BB * NN, 64>>>(kernel_points);
    gemm_kernel<<<BB * NN / 128, 256>>>(kernel_w, bias, out);
}